// round 14
// baseline (speedup 1.0000x reference)
#include <cuda_runtime.h>
#include <cuda_fp16.h>
#include <cstdint>

// ---------------- problem constants ----------------
#define N_TOK   16384
#define DIM     1024
#define HEADS   8
#define DHEAD   64
#define HD      (HEADS * DHEAD)   // 512
#define QKVW    (3 * HD)          // 1536
#define WSZ     128
#define NWIN    (N_TOK / WSZ)     // 128

// ---------------- scratch ----------------
__device__ __half g_xh[(size_t)N_TOK * DIM];      // x -> half
__device__ __half g_wqkvT[(size_t)QKVW * DIM];    // w_qkv^T half  [1536][1024]
__device__ __half g_woutT[(size_t)DIM * HD];      // w_out^T half  [1024][512]
__device__ __half g_qkvh[(size_t)N_TOK * QKVW];   // GEMM1 out half
__device__ __half g_attnh[(size_t)N_TOK * HD];    // attention out half
__device__ __align__(16) __half g_zero16[8];      // 16B of zeros, 16B-aligned (cp.async src)

// ---------------- helpers ----------------
__device__ __forceinline__ unsigned h2u(__half2 h) {
    return *reinterpret_cast<unsigned*>(&h);
}

__device__ __forceinline__ void mma_f16(float c[4], unsigned a0, unsigned a1,
                                        unsigned a2, unsigned a3,
                                        unsigned b0, unsigned b1) {
    asm volatile(
        "mma.sync.aligned.m16n8k16.row.col.f32.f16.f16.f32 "
        "{%0,%1,%2,%3}, {%4,%5,%6,%7}, {%8,%9}, {%0,%1,%2,%3};"
        : "+f"(c[0]), "+f"(c[1]), "+f"(c[2]), "+f"(c[3])
        : "r"(a0), "r"(a1), "r"(a2), "r"(a3), "r"(b0), "r"(b1));
}

__device__ __forceinline__ void ldsm4(unsigned& r0, unsigned& r1,
                                      unsigned& r2, unsigned& r3, unsigned addr) {
    asm volatile("ldmatrix.sync.aligned.m8n8.x4.shared.b16 {%0,%1,%2,%3}, [%4];"
                 : "=r"(r0), "=r"(r1), "=r"(r2), "=r"(r3) : "r"(addr));
}

__device__ __forceinline__ void ldsm4t(unsigned& r0, unsigned& r1,
                                       unsigned& r2, unsigned& r3, unsigned addr) {
    asm volatile("ldmatrix.sync.aligned.m8n8.x4.trans.shared.b16 {%0,%1,%2,%3}, [%4];"
                 : "=r"(r0), "=r"(r1), "=r"(r2), "=r"(r3) : "r"(addr));
}

__global__ void cvt_f2h(const float4* __restrict__ in,
                        __half2* __restrict__ out, int n4)
{
    int i = blockIdx.x * blockDim.x + threadIdx.x;
    if (i < n4) {
        float4 v = in[i];
        out[2 * i + 0] = __floats2half2_rn(v.x, v.y);
        out[2 * i + 1] = __floats2half2_rn(v.z, v.w);
    }
}

// in[R][C] fp32 -> out[C][R] half. block (32,8), grid (C/32, R/32).
__global__ void transpose_f2h(const float* __restrict__ in,
                              __half* __restrict__ out, int R, int C)
{
    __shared__ float t[32][33];
    int bx = blockIdx.x * 32, by = blockIdx.y * 32;
    int x = bx + threadIdx.x;
#pragma unroll
    for (int i = 0; i < 32; i += 8) {
        int y = by + threadIdx.y + i;
        t[threadIdx.y + i][threadIdx.x] = in[(size_t)y * C + x];
    }
    __syncthreads();
    int xo = by + threadIdx.x;
#pragma unroll
    for (int i = 0; i < 32; i += 8) {
        int yo = bx + threadIdx.y + i;
        out[(size_t)yo * R + xo] = __float2half_rn(t[threadIdx.x][threadIdx.y + i]);
    }
}

// ---------------- FP16 tensor-core GEMM ----------------
// C[M,N] = A[M,K] @ Bt[N,K]^T (+bias). A, Bt half row-major.
// CTA tile 128x256x64(halves), 8 warps 2x4 (warp tile 64x64),
// 3-stage cp.async pipeline (wait_group 1, prefetch distance 2),
// ldmatrix.x4 fragment loads. smem row r = 64 halves, 16B chunk c at c^(r&7).
// Stage s at byte offset s*49152; A [0,16384), B [16384,49152) within stage.
#define CPA16(dst, src) \
    asm volatile("cp.async.cg.shared.global [%0], [%1], 16;" :: "r"(dst), "l"(src))

#define STAGE_B 49152                      // bytes per stage (A 16K + B 32K)
#define HG_SMEM (3 * STAGE_B)              // 147456 bytes

template <bool WITH_BIAS, bool HALF_OUT>
__global__ __launch_bounds__(256, 1)
void h16gemm(const __half* __restrict__ A, const __half* __restrict__ Bt,
             const float* __restrict__ bias, void* __restrict__ Cout,
             int M, int N, int K)
{
    extern __shared__ __half hsm[];
    const unsigned smBase = (unsigned)__cvta_generic_to_shared(hsm);

    const int tid  = threadIdx.x;
    const int lane = tid & 31;
    const int wid  = tid >> 5;
    const int wm   = wid >> 2;          // 0..1  (64-row slabs)
    const int wn   = wid & 3;           // 0..3  (64-col slabs)
    const int g    = lane >> 2;         // 0..7
    const int tg   = lane & 3;          // 0..3

    const int row0 = blockIdx.y * 128;
    const int col0 = blockIdx.x * 256;
    const int NKT  = K / 64;

    float acc[4][8][4];
#pragma unroll
    for (int mi = 0; mi < 4; ++mi)
#pragma unroll
        for (int ni = 0; ni < 8; ++ni)
#pragma unroll
            for (int r = 0; r < 4; ++r) acc[mi][ni][r] = 0.f;

    auto issue = [&](int kt, int s) {
        const unsigned sb = smBase + (unsigned)s * STAGE_B;
#pragma unroll
        for (int p = 0; p < 4; ++p) {       // A: 128 rows x 8 chunks = 1024 / 256 thr
            int idx = p * 256 + tid;
            int r = idx >> 3, c = idx & 7;
            CPA16(sb + (unsigned)(r * 128 + ((c ^ (r & 7)) * 16)),
                  A + (size_t)(row0 + r) * K + kt * 64 + c * 8);
        }
#pragma unroll
        for (int p = 0; p < 8; ++p) {       // B: 256 rows x 8 chunks = 2048 / 256 thr
            int idx = p * 256 + tid;
            int r = idx >> 3, c = idx & 7;
            CPA16(sb + 16384u + (unsigned)(r * 128 + ((c ^ (r & 7)) * 16)),
                  Bt + (size_t)(col0 + r) * K + kt * 64 + c * 8);
        }
        asm volatile("cp.async.commit_group;");
    };

    issue(0, 0);
    issue(1, 1);

    // ldmatrix lane decomposition (constant per thread)
    const int lr  = lane & 15;          // row-in-tile for A
    const int lc  = lane >> 4;          // chunk parity for A
    const int bn8 = 8 * (lane >> 4) + (lane & 7);   // B row offset within 16
    const int bcp = (lane >> 3) & 1;                // B chunk parity

    for (int kt = 0; kt < NKT; ++kt) {
        const int s = kt % 3;
        if (kt + 1 < NKT) asm volatile("cp.async.wait_group 1;");
        else              asm volatile("cp.async.wait_group 0;");
        __syncthreads();
        if (kt + 2 < NKT) issue(kt + 2, (kt + 2) % 3);

        const unsigned sA = smBase + (unsigned)s * STAGE_B;
        const unsigned sB = sA + 16384u;

#pragma unroll
        for (int ks = 0; ks < 4; ++ks) {
            unsigned a[4][4];
#pragma unroll
            for (int mi = 0; mi < 4; ++mi) {
                int m = wm * 64 + mi * 16 + lr;
                int c = 2 * ks + lc;
                ldsm4(a[mi][0], a[mi][1], a[mi][2], a[mi][3],
                      sA + (unsigned)(2 * (m * 64 + ((c ^ (m & 7)) << 3))));
            }
            unsigned b[8][2];
#pragma unroll
            for (int blk = 0; blk < 4; ++blk) {
                int n = wn * 64 + 16 * blk + bn8;
                int c = 2 * ks + bcp;
                ldsm4(b[2 * blk][0], b[2 * blk][1], b[2 * blk + 1][0], b[2 * blk + 1][1],
                      sB + (unsigned)(2 * (n * 64 + ((c ^ (n & 7)) << 3))));
            }
#pragma unroll
            for (int mi = 0; mi < 4; ++mi)
#pragma unroll
                for (int ni = 0; ni < 8; ++ni)
                    mma_f16(acc[mi][ni], a[mi][0], a[mi][1], a[mi][2], a[mi][3],
                            b[ni][0], b[ni][1]);
        }
        __syncthreads();
    }

    // epilogue
#pragma unroll
    for (int ni = 0; ni < 8; ++ni) {
        int col = col0 + wn * 64 + ni * 8 + 2 * tg;
        float bx = 0.f, by = 0.f;
        if (WITH_BIAS) { bx = bias[col]; by = bias[col + 1]; }
#pragma unroll
        for (int mi = 0; mi < 4; ++mi) {
            int row = row0 + wm * 64 + mi * 16 + g;
            if (HALF_OUT) {
                __half* C = (__half*)Cout;
                __half2 h0 = __floats2half2_rn(acc[mi][ni][0], acc[mi][ni][1]);
                __half2 h1 = __floats2half2_rn(acc[mi][ni][2], acc[mi][ni][3]);
                *reinterpret_cast<__half2*>(&C[(size_t)row * N + col]) = h0;
                *reinterpret_cast<__half2*>(&C[(size_t)(row + 8) * N + col]) = h1;
            } else {
                float* C = (float*)Cout;
                float2 v0 = make_float2(acc[mi][ni][0] + bx, acc[mi][ni][1] + by);
                float2 v1 = make_float2(acc[mi][ni][2] + bx, acc[mi][ni][3] + by);
                *reinterpret_cast<float2*>(&C[(size_t)row * N + col]) = v0;
                *reinterpret_cast<float2*>(&C[(size_t)(row + 8) * N + col]) = v1;
            }
        }
    }
}

// ---------------- FP16 tensor-core attention (round-12/13, passed) ----------------
// One CTA per (window, head), 256 threads (8 warps x 16 query rows).
// smem (halves), all "row r, chunk c at c^(r&7)" swizzled:
//   qs [128][64] @0, ks [256][64] @8192, vs [256][64] @24576.
// Q/K cp.async (group A), V cp.async (group B) overlapped under S+softmax.
// PV uses ldmatrix.x4.trans on row-major V.
#define ATTN_SMEM_B (40960 * 2)            // 81920 bytes

__global__ __launch_bounds__(256)
void attn_h16_kernel(const __half* __restrict__ qkv, __half* __restrict__ o)
{
    extern __shared__ __half hs[];
    const unsigned smB = (unsigned)__cvta_generic_to_shared(hs);
    const unsigned qsB = smB;
    const unsigned ksB = smB + 8192u * 2u;
    const unsigned vsB = smB + 24576u * 2u;

    const int w    = blockIdx.x;
    const int h    = blockIdx.y;
    const int tid  = threadIdx.x;
    const int lane = tid & 31;
    const int wq   = tid >> 5;
    const int g    = lane >> 2;
    const int tg   = lane & 3;
    const int m0   = wq * 16;
    const int tok0 = w * WSZ;

    // ---- group A: Q (1024 chunks) + K (2048 chunks) ----
#pragma unroll
    for (int p = 0; p < 4; ++p) {
        int idx = p * 256 + tid;
        int row = idx >> 3, c = idx & 7;
        CPA16(qsB + (unsigned)(row * 128 + ((c ^ (row & 7)) * 16)),
              qkv + (size_t)(tok0 + row) * QKVW + h * DHEAD + c * 8);
    }
#pragma unroll
    for (int p = 0; p < 8; ++p) {
        int idx = p * 256 + tid;
        int j = idx >> 3, c = idx & 7;
        const __half* src = (w == 0 && j < WSZ)
            ? g_zero16
            : qkv + (size_t)(tok0 - WSZ + j) * QKVW + HD + h * DHEAD + c * 8;
        CPA16(ksB + (unsigned)(j * 128 + ((c ^ (j & 7)) * 16)), src);
    }
    asm volatile("cp.async.commit_group;");

    // ---- group B: V (2048 chunks) ----
#pragma unroll
    for (int p = 0; p < 8; ++p) {
        int idx = p * 256 + tid;
        int j = idx >> 3, c = idx & 7;
        const __half* src = (w == 0 && j < WSZ)
            ? g_zero16
            : qkv + (size_t)(tok0 - WSZ + j) * QKVW + 2 * HD + h * DHEAD + c * 8;
        CPA16(vsB + (unsigned)(j * 128 + ((c ^ (j & 7)) * 16)), src);
    }
    asm volatile("cp.async.commit_group;");

    asm volatile("cp.async.wait_group 1;");   // Q + K ready
    __syncthreads();

    // ldmatrix lane decomposition
    const int lr  = lane & 15;
    const int lc  = lane >> 4;
    const int bn8 = 8 * (lane >> 4) + (lane & 7);
    const int bcp = (lane >> 3) & 1;
    const int rr   = lane & 7;            // trans-ldsm row within tile
    const int tsel = lane >> 3;           // trans-ldsm tile select 0..3

    // ---- Q A-fragments ----
    unsigned qa[4][4];
#pragma unroll
    for (int ks = 0; ks < 4; ++ks) {
        int m = m0 + lr;
        int c = 2 * ks + lc;
        ldsm4(qa[ks][0], qa[ks][1], qa[ks][2], qa[ks][3],
              qsB + (unsigned)(2 * (m * 64 + ((c ^ (m & 7)) << 3))));
    }

    // ---- S = Q @ K^T ----
    float s[32][4];
#pragma unroll
    for (int nt = 0; nt < 32; ++nt) {
        s[nt][0] = 0.f; s[nt][1] = 0.f; s[nt][2] = 0.f; s[nt][3] = 0.f;
    }
#pragma unroll
    for (int ntp = 0; ntp < 16; ++ntp) {
        const int jb = 16 * ntp + bn8;
#pragma unroll
        for (int ks = 0; ks < 4; ++ks) {
            int c = 2 * ks + bcp;
            unsigned b0, b1, b2, b3;
            ldsm4(b0, b1, b2, b3,
                  ksB + (unsigned)(2 * (jb * 64 + ((c ^ (jb & 7)) << 3))));
            mma_f16(s[2 * ntp],     qa[ks][0], qa[ks][1], qa[ks][2], qa[ks][3], b0, b1);
            mma_f16(s[2 * ntp + 1], qa[ks][0], qa[ks][1], qa[ks][2], qa[ks][3], b2, b3);
        }
    }

    // ---- scale (d^-1/2 = 0.125) + mask + softmax ----
    const int i_lo = m0 + g, i_hi = i_lo + 8;
    float mx0 = -3.0e38f, mx1 = -3.0e38f;
#pragma unroll
    for (int nt = 0; nt < 32; ++nt) {
        int j0 = 8 * nt + 2 * tg, j1 = j0 + 1;
        s[nt][0] = (j0 > i_lo + WSZ) ? -1e10f : s[nt][0] * 0.125f;
        s[nt][1] = (j1 > i_lo + WSZ) ? -1e10f : s[nt][1] * 0.125f;
        s[nt][2] = (j0 > i_hi + WSZ) ? -1e10f : s[nt][2] * 0.125f;
        s[nt][3] = (j1 > i_hi + WSZ) ? -1e10f : s[nt][3] * 0.125f;
        mx0 = fmaxf(mx0, fmaxf(s[nt][0], s[nt][1]));
        mx1 = fmaxf(mx1, fmaxf(s[nt][2], s[nt][3]));
    }
    mx0 = fmaxf(mx0, __shfl_xor_sync(0xffffffffu, mx0, 1));
    mx0 = fmaxf(mx0, __shfl_xor_sync(0xffffffffu, mx0, 2));
    mx1 = fmaxf(mx1, __shfl_xor_sync(0xffffffffu, mx1, 1));
    mx1 = fmaxf(mx1, __shfl_xor_sync(0xffffffffu, mx1, 2));

    float l0 = 0.f, l1 = 0.f;
    unsigned ph[32][2];
#pragma unroll
    for (int nt = 0; nt < 32; ++nt) {
        float p0 = __expf(s[nt][0] - mx0);
        float p1 = __expf(s[nt][1] - mx0);
        float p2 = __expf(s[nt][2] - mx1);
        float p3 = __expf(s[nt][3] - mx1);
        l0 += p0 + p1;
        l1 += p2 + p3;
        ph[nt][0] = h2u(__floats2half2_rn(p0, p1));
        ph[nt][1] = h2u(__floats2half2_rn(p2, p3));
    }
    l0 += __shfl_xor_sync(0xffffffffu, l0, 1);
    l0 += __shfl_xor_sync(0xffffffffu, l0, 2);
    l1 += __shfl_xor_sync(0xffffffffu, l1, 1);
    l1 += __shfl_xor_sync(0xffffffffu, l1, 2);

    asm volatile("cp.async.wait_group 0;");   // V ready (loaded under S+softmax)
    __syncthreads();

    // ---- O = P @ V : trans-ldmatrix B fragments straight from row-major V ----
    float ov[8][4];
#pragma unroll
    for (int nt = 0; nt < 8; ++nt) {
        ov[nt][0] = 0.f; ov[nt][1] = 0.f; ov[nt][2] = 0.f; ov[nt][3] = 0.f;
    }
#pragma unroll
    for (int kj = 0; kj < 16; ++kj) {
        unsigned a0 = ph[2 * kj][0];
        unsigned a1 = ph[2 * kj][1];
        unsigned a2 = ph[2 * kj + 1][0];
        unsigned a3 = ph[2 * kj + 1][1];
        const int row = 16 * kj + 8 * (tsel & 1) + rr;
#pragma unroll
        for (int ntp = 0; ntp < 4; ++ntp) {
            int ch = 2 * ntp + (tsel >> 1);
            unsigned b0, b1, b2, b3;
            ldsm4t(b0, b1, b2, b3,
                   vsB + (unsigned)(2 * (row * 64 + ((ch ^ (row & 7)) << 3))));
            mma_f16(ov[2 * ntp],     a0, a1, a2, a3, b0, b1);
            mma_f16(ov[2 * ntp + 1], a0, a1, a2, a3, b2, b3);
        }
    }

    // ---- normalize + write half ----
    float inv0 = 1.f / l0, inv1 = 1.f / l1;
    const int row_lo = tok0 + m0 + g;
#pragma unroll
    for (int nt = 0; nt < 8; ++nt) {
        int col = h * DHEAD + 8 * nt + 2 * tg;
        __half2 h0 = __floats2half2_rn(ov[nt][0] * inv0, ov[nt][1] * inv0);
        __half2 h1 = __floats2half2_rn(ov[nt][2] * inv1, ov[nt][3] * inv1);
        *reinterpret_cast<__half2*>(&o[(size_t)row_lo * HD + col]) = h0;
        *reinterpret_cast<__half2*>(&o[(size_t)(row_lo + 8) * HD + col]) = h1;
    }
}

// ---------------- launch ----------------
extern "C" void kernel_launch(void* const* d_in, const int* in_sizes, int n_in,
                              void* d_out, int out_size)
{
    (void)in_sizes; (void)n_in; (void)out_size;
    const float* x     = (const float*)d_in[0];  // [16384, 1024]
    const float* w_qkv = (const float*)d_in[1];  // [1024, 1536]
    const float* w_out = (const float*)d_in[2];  // [512, 1024]
    const float* b_out = (const float*)d_in[3];  // [1024]
    float*       out   = (float*)d_out;          // [16384, 1024]

    __half *xh, *wqkvT, *woutT, *qkvh, *attnh;
    cudaGetSymbolAddress((void**)&xh,    g_xh);
    cudaGetSymbolAddress((void**)&wqkvT, g_wqkvT);
    cudaGetSymbolAddress((void**)&woutT, g_woutT);
    cudaGetSymbolAddress((void**)&qkvh,  g_qkvh);
    cudaGetSymbolAddress((void**)&attnh, g_attnh);

    cudaFuncSetAttribute((const void*)h16gemm<false, true>,
                         cudaFuncAttributeMaxDynamicSharedMemorySize, HG_SMEM);
    cudaFuncSetAttribute((const void*)h16gemm<true, false>,
                         cudaFuncAttributeMaxDynamicSharedMemorySize, HG_SMEM);
    cudaFuncSetAttribute((const void*)attn_h16_kernel,
                         cudaFuncAttributeMaxDynamicSharedMemorySize, ATTN_SMEM_B);

    // 0) convert x -> half; transpose+convert weights -> half
    {
        int n4 = N_TOK * DIM / 4;
        cvt_f2h<<<(n4 + 255) / 256, 256>>>((const float4*)x, (__half2*)xh, n4);
        transpose_f2h<<<dim3(QKVW / 32, DIM / 32), dim3(32, 8)>>>(w_qkv, wqkvT, DIM, QKVW);
        transpose_f2h<<<dim3(DIM / 32, HD / 32),  dim3(32, 8)>>>(w_out, woutT, HD, DIM);
    }

    // 1) QKV projection: [16384,1024] @ [1024,1536], half out
    {
        dim3 grid(QKVW / 256, N_TOK / 128);   // (6, 128)
        h16gemm<false, true><<<grid, 256, HG_SMEM>>>(xh, wqkvT, nullptr, qkvh,
                                                     N_TOK, QKVW, DIM);
    }

    // 2) windowed look-back attention (fp16 mma, fp32 softmax)
    {
        dim3 grid(NWIN, HEADS);
        attn_h16_kernel<<<grid, 256, ATTN_SMEM_B>>>(qkvh, attnh);
    }

    // 3) output projection: [16384,512] @ [512,1024] + bias, fp32 out
    {
        dim3 grid(DIM / 256, N_TOK / 128);    // (4, 128)
        h16gemm<true, false><<<grid, 256, HG_SMEM>>>(attnh, woutT, b_out, out,
                                                     N_TOK, DIM, HD);
    }
}

// round 15
// speedup vs baseline: 1.1719x; 1.1719x over previous
#include <cuda_runtime.h>
#include <cuda_fp16.h>
#include <cstdint>

// ---------------- problem constants ----------------
#define N_TOK   16384
#define DIM     1024
#define HEADS   8
#define DHEAD   64
#define HD      (HEADS * DHEAD)   // 512
#define QKVW    (3 * HD)          // 1536
#define WSZ     128
#define NWIN    (N_TOK / WSZ)     // 128

// ---------------- scratch ----------------
__device__ __half g_xh[(size_t)N_TOK * DIM];      // x -> half
__device__ __half g_wqkvT[(size_t)QKVW * DIM];    // w_qkv^T half  [1536][1024]
__device__ __half g_woutT[(size_t)DIM * HD];      // w_out^T half  [1024][512]
__device__ __half g_qkvh[(size_t)N_TOK * QKVW];   // GEMM1 out half
__device__ __half g_attnh[(size_t)N_TOK * HD];    // attention out half
__device__ __align__(16) __half g_zero16[8];      // 16B of zeros (cp.async src)

// ---------------- helpers ----------------
__device__ __forceinline__ unsigned h2u(__half2 h) {
    return *reinterpret_cast<unsigned*>(&h);
}

__device__ __forceinline__ void mma_f16(float c[4], unsigned a0, unsigned a1,
                                        unsigned a2, unsigned a3,
                                        unsigned b0, unsigned b1) {
    asm volatile(
        "mma.sync.aligned.m16n8k16.row.col.f32.f16.f16.f32 "
        "{%0,%1,%2,%3}, {%4,%5,%6,%7}, {%8,%9}, {%0,%1,%2,%3};"
        : "+f"(c[0]), "+f"(c[1]), "+f"(c[2]), "+f"(c[3])
        : "r"(a0), "r"(a1), "r"(a2), "r"(a3), "r"(b0), "r"(b1));
}

__device__ __forceinline__ void ldsm4(unsigned& r0, unsigned& r1,
                                      unsigned& r2, unsigned& r3, unsigned addr) {
    asm volatile("ldmatrix.sync.aligned.m8n8.x4.shared.b16 {%0,%1,%2,%3}, [%4];"
                 : "=r"(r0), "=r"(r1), "=r"(r2), "=r"(r3) : "r"(addr));
}

__device__ __forceinline__ void ldsm4t(unsigned& r0, unsigned& r1,
                                       unsigned& r2, unsigned& r3, unsigned addr) {
    asm volatile("ldmatrix.sync.aligned.m8n8.x4.trans.shared.b16 {%0,%1,%2,%3}, [%4];"
                 : "=r"(r0), "=r"(r1), "=r"(r2), "=r"(r3) : "r"(addr));
}

// ---------------- fused prepass: cvt x + transpose both weights ----------------
// blocks [0, XB)                : x fp32 -> half (float4 granules)
// blocks [XB, XB+T1)            : w_qkv [1024][1536] -> wqkvT [1536][1024]
// blocks [XB+T1, XB+T1+T2)      : w_out [512][1024]  -> woutT [1024][512]
#define XB  (N_TOK * DIM / 4 / 256)            // 16384 blocks
#define T1X (QKVW / 32)                        // 48
#define T1Y (DIM / 32)                         // 32
#define T2X (DIM / 32)                         // 32
#define T2Y (HD / 32)                          // 16
#define PREP_BLOCKS (XB + T1X * T1Y + T2X * T2Y)

__global__ __launch_bounds__(256)
void prepass_kernel(const float* __restrict__ x, const float* __restrict__ w_qkv,
                    const float* __restrict__ w_out)
{
    int b = blockIdx.x;
    if (b < XB) {
        int i = b * 256 + threadIdx.x;
        float4 v = reinterpret_cast<const float4*>(x)[i];
        __half2* out = reinterpret_cast<__half2*>(g_xh);
        out[2 * i + 0] = __floats2half2_rn(v.x, v.y);
        out[2 * i + 1] = __floats2half2_rn(v.z, v.w);
        return;
    }
    __shared__ float t[32][33];
    const float* in;
    __half* out;
    int R, C, bx, by;
    if (b < XB + T1X * T1Y) {
        int bb = b - XB;
        in = w_qkv; out = g_wqkvT; R = DIM; C = QKVW;
        bx = (bb % T1X) * 32; by = (bb / T1X) * 32;
    } else {
        int bb = b - XB - T1X * T1Y;
        in = w_out; out = g_woutT; R = HD; C = DIM;
        bx = (bb % T2X) * 32; by = (bb / T2X) * 32;
    }
    int tx = threadIdx.x & 31, ty = threadIdx.x >> 5;   // 32 x 8
    int xcol = bx + tx;
#pragma unroll
    for (int i = 0; i < 32; i += 8) {
        int y = by + ty + i;
        t[ty + i][tx] = in[(size_t)y * C + xcol];
    }
    __syncthreads();
    int xo = by + tx;
#pragma unroll
    for (int i = 0; i < 32; i += 8) {
        int yo = bx + ty + i;
        out[(size_t)yo * R + xo] = __float2half_rn(t[tx][ty + i]);
    }
}

// ---------------- FP16 tensor-core GEMM (round-13 config, one barrier per k-tile) ----------------
// C[M,N] = A[M,K] @ Bt[N,K]^T (+bias). CTA 128x128x64(halves), 8 warps 2x4,
// 3-stage cp.async (wait_group 1, prefetch distance 2), ldmatrix.x4 loads.
// smem row r = 64 halves, 16B chunk c at c^(r&7). Stage s at byte s*32768;
// A [0,16384), B [16384,32768) within stage.
#define CPA16(dst, src) \
    asm volatile("cp.async.cg.shared.global [%0], [%1], 16;" :: "r"(dst), "l"(src))

#define HSTAGE 16384                       // halves per stage (A 8192 + B 8192)
#define HG_SMEM (3 * HSTAGE * 2)           // 98304 bytes

template <bool WITH_BIAS, bool HALF_OUT>
__global__ __launch_bounds__(256, 2)
void h16gemm(const __half* __restrict__ A, const __half* __restrict__ Bt,
             const float* __restrict__ bias, void* __restrict__ Cout,
             int M, int N, int K)
{
    extern __shared__ __half hsm[];
    const unsigned smBase = (unsigned)__cvta_generic_to_shared(hsm);

    const int tid  = threadIdx.x;
    const int lane = tid & 31;
    const int wid  = tid >> 5;
    const int wm   = wid >> 2;          // 0..1
    const int wn   = wid & 3;           // 0..3
    const int g    = lane >> 2;         // 0..7
    const int tg   = lane & 3;          // 0..3

    const int row0 = blockIdx.y * 128;
    const int col0 = blockIdx.x * 128;
    const int NKT  = K / 64;

    float acc[4][4][4];
#pragma unroll
    for (int mi = 0; mi < 4; ++mi)
#pragma unroll
        for (int ni = 0; ni < 4; ++ni)
#pragma unroll
            for (int r = 0; r < 4; ++r) acc[mi][ni][r] = 0.f;

    auto issue = [&](int kt, int s) {
        const unsigned sb = smBase + (unsigned)s * (HSTAGE * 2);
#pragma unroll
        for (int p = 0; p < 4; ++p) {       // A: 1024 chunks / 256 thr
            int idx = p * 256 + tid;
            int r = idx >> 3, c = idx & 7;
            CPA16(sb + (unsigned)(r * 128 + ((c ^ (r & 7)) * 16)),
                  A + (size_t)(row0 + r) * K + kt * 64 + c * 8);
        }
#pragma unroll
        for (int p = 0; p < 4; ++p) {       // B: 1024 chunks
            int idx = p * 256 + tid;
            int r = idx >> 3, c = idx & 7;
            CPA16(sb + 16384u + (unsigned)(r * 128 + ((c ^ (r & 7)) * 16)),
                  Bt + (size_t)(col0 + r) * K + kt * 64 + c * 8);
        }
        asm volatile("cp.async.commit_group;");
    };

    issue(0, 0);
    issue(1, 1);

    // ldmatrix lane decomposition
    const int lr  = lane & 15;
    const int lc  = lane >> 4;
    const int bn8 = 8 * (lane >> 4) + (lane & 7);
    const int bcp = (lane >> 3) & 1;

    for (int kt = 0; kt < NKT; ++kt) {
        const int s = kt % 3;
        if (kt + 1 < NKT) asm volatile("cp.async.wait_group 1;");
        else              asm volatile("cp.async.wait_group 0;");
        __syncthreads();   // sole barrier: publishes group kt AND protects stage (kt+2)%3
                           // (its prior readers were compute(kt-1), ordered by this barrier)
        if (kt + 2 < NKT) issue(kt + 2, (kt + 2) % 3);

        const unsigned sA = smBase + (unsigned)s * (HSTAGE * 2);
        const unsigned sB = sA + 16384u;

#pragma unroll
        for (int ks = 0; ks < 4; ++ks) {
            unsigned a[4][4];
#pragma unroll
            for (int mi = 0; mi < 4; ++mi) {
                int m = wm * 64 + mi * 16 + lr;
                int c = 2 * ks + lc;
                ldsm4(a[mi][0], a[mi][1], a[mi][2], a[mi][3],
                      sA + (unsigned)(2 * (m * 64 + ((c ^ (m & 7)) << 3))));
            }
            unsigned b[4][2];
#pragma unroll
            for (int blk = 0; blk < 2; ++blk) {
                int n = wn * 32 + 16 * blk + bn8;
                int c = 2 * ks + bcp;
                ldsm4(b[2 * blk][0], b[2 * blk][1], b[2 * blk + 1][0], b[2 * blk + 1][1],
                      sB + (unsigned)(2 * (n * 64 + ((c ^ (n & 7)) << 3))));
            }
#pragma unroll
            for (int mi = 0; mi < 4; ++mi)
#pragma unroll
                for (int ni = 0; ni < 4; ++ni)
                    mma_f16(acc[mi][ni], a[mi][0], a[mi][1], a[mi][2], a[mi][3],
                            b[ni][0], b[ni][1]);
        }
        // no loop-end barrier: next iteration's top barrier covers the hazard
    }

    // epilogue
#pragma unroll
    for (int ni = 0; ni < 4; ++ni) {
        int col = col0 + wn * 32 + ni * 8 + 2 * tg;
        float bx = 0.f, by = 0.f;
        if (WITH_BIAS) { bx = bias[col]; by = bias[col + 1]; }
#pragma unroll
        for (int mi = 0; mi < 4; ++mi) {
            int row = row0 + wm * 64 + mi * 16 + g;
            if (HALF_OUT) {
                __half* C = (__half*)Cout;
                __half2 h0 = __floats2half2_rn(acc[mi][ni][0], acc[mi][ni][1]);
                __half2 h1 = __floats2half2_rn(acc[mi][ni][2], acc[mi][ni][3]);
                *reinterpret_cast<__half2*>(&C[(size_t)row * N + col]) = h0;
                *reinterpret_cast<__half2*>(&C[(size_t)(row + 8) * N + col]) = h1;
            } else {
                float* C = (float*)Cout;
                float2 v0 = make_float2(acc[mi][ni][0] + bx, acc[mi][ni][1] + by);
                float2 v1 = make_float2(acc[mi][ni][2] + bx, acc[mi][ni][3] + by);
                *reinterpret_cast<float2*>(&C[(size_t)row * N + col]) = v0;
                *reinterpret_cast<float2*>(&C[(size_t)(row + 8) * N + col]) = v1;
            }
        }
    }
}

// ---------------- FP16 tensor-core attention (round-13, passed) ----------------
#define ATTN_SMEM_B (40960 * 2)            // 81920 bytes

__global__ __launch_bounds__(256)
void attn_h16_kernel(const __half* __restrict__ qkv, __half* __restrict__ o)
{
    extern __shared__ __half hs[];
    const unsigned smB = (unsigned)__cvta_generic_to_shared(hs);
    const unsigned qsB = smB;
    const unsigned ksB = smB + 8192u * 2u;
    const unsigned vsB = smB + 24576u * 2u;

    const int w    = blockIdx.x;
    const int h    = blockIdx.y;
    const int tid  = threadIdx.x;
    const int lane = tid & 31;
    const int wq   = tid >> 5;
    const int g    = lane >> 2;
    const int tg   = lane & 3;
    const int m0   = wq * 16;
    const int tok0 = w * WSZ;

    // ---- group A: Q + K ----
#pragma unroll
    for (int p = 0; p < 4; ++p) {
        int idx = p * 256 + tid;
        int row = idx >> 3, c = idx & 7;
        CPA16(qsB + (unsigned)(row * 128 + ((c ^ (row & 7)) * 16)),
              qkv + (size_t)(tok0 + row) * QKVW + h * DHEAD + c * 8);
    }
#pragma unroll
    for (int p = 0; p < 8; ++p) {
        int idx = p * 256 + tid;
        int j = idx >> 3, c = idx & 7;
        const __half* src = (w == 0 && j < WSZ)
            ? g_zero16
            : qkv + (size_t)(tok0 - WSZ + j) * QKVW + HD + h * DHEAD + c * 8;
        CPA16(ksB + (unsigned)(j * 128 + ((c ^ (j & 7)) * 16)), src);
    }
    asm volatile("cp.async.commit_group;");

    // ---- group B: V ----
#pragma unroll
    for (int p = 0; p < 8; ++p) {
        int idx = p * 256 + tid;
        int j = idx >> 3, c = idx & 7;
        const __half* src = (w == 0 && j < WSZ)
            ? g_zero16
            : qkv + (size_t)(tok0 - WSZ + j) * QKVW + 2 * HD + h * DHEAD + c * 8;
        CPA16(vsB + (unsigned)(j * 128 + ((c ^ (j & 7)) * 16)), src);
    }
    asm volatile("cp.async.commit_group;");

    asm volatile("cp.async.wait_group 1;");
    __syncthreads();

    const int lr  = lane & 15;
    const int lc  = lane >> 4;
    const int bn8 = 8 * (lane >> 4) + (lane & 7);
    const int bcp = (lane >> 3) & 1;
    const int rr   = lane & 7;
    const int tsel = lane >> 3;

    unsigned qa[4][4];
#pragma unroll
    for (int ks = 0; ks < 4; ++ks) {
        int m = m0 + lr;
        int c = 2 * ks + lc;
        ldsm4(qa[ks][0], qa[ks][1], qa[ks][2], qa[ks][3],
              qsB + (unsigned)(2 * (m * 64 + ((c ^ (m & 7)) << 3))));
    }

    float s[32][4];
#pragma unroll
    for (int nt = 0; nt < 32; ++nt) {
        s[nt][0] = 0.f; s[nt][1] = 0.f; s[nt][2] = 0.f; s[nt][3] = 0.f;
    }
#pragma unroll
    for (int ntp = 0; ntp < 16; ++ntp) {
        const int jb = 16 * ntp + bn8;
#pragma unroll
        for (int ks = 0; ks < 4; ++ks) {
            int c = 2 * ks + bcp;
            unsigned b0, b1, b2, b3;
            ldsm4(b0, b1, b2, b3,
                  ksB + (unsigned)(2 * (jb * 64 + ((c ^ (jb & 7)) << 3))));
            mma_f16(s[2 * ntp],     qa[ks][0], qa[ks][1], qa[ks][2], qa[ks][3], b0, b1);
            mma_f16(s[2 * ntp + 1], qa[ks][0], qa[ks][1], qa[ks][2], qa[ks][3], b2, b3);
        }
    }

    const int i_lo = m0 + g, i_hi = i_lo + 8;
    float mx0 = -3.0e38f, mx1 = -3.0e38f;
#pragma unroll
    for (int nt = 0; nt < 32; ++nt) {
        int j0 = 8 * nt + 2 * tg, j1 = j0 + 1;
        s[nt][0] = (j0 > i_lo + WSZ) ? -1e10f : s[nt][0] * 0.125f;
        s[nt][1] = (j1 > i_lo + WSZ) ? -1e10f : s[nt][1] * 0.125f;
        s[nt][2] = (j0 > i_hi + WSZ) ? -1e10f : s[nt][2] * 0.125f;
        s[nt][3] = (j1 > i_hi + WSZ) ? -1e10f : s[nt][3] * 0.125f;
        mx0 = fmaxf(mx0, fmaxf(s[nt][0], s[nt][1]));
        mx1 = fmaxf(mx1, fmaxf(s[nt][2], s[nt][3]));
    }
    mx0 = fmaxf(mx0, __shfl_xor_sync(0xffffffffu, mx0, 1));
    mx0 = fmaxf(mx0, __shfl_xor_sync(0xffffffffu, mx0, 2));
    mx1 = fmaxf(mx1, __shfl_xor_sync(0xffffffffu, mx1, 1));
    mx1 = fmaxf(mx1, __shfl_xor_sync(0xffffffffu, mx1, 2));

    float l0 = 0.f, l1 = 0.f;
    unsigned ph[32][2];
#pragma unroll
    for (int nt = 0; nt < 32; ++nt) {
        float p0 = __expf(s[nt][0] - mx0);
        float p1 = __expf(s[nt][1] - mx0);
        float p2 = __expf(s[nt][2] - mx1);
        float p3 = __expf(s[nt][3] - mx1);
        l0 += p0 + p1;
        l1 += p2 + p3;
        ph[nt][0] = h2u(__floats2half2_rn(p0, p1));
        ph[nt][1] = h2u(__floats2half2_rn(p2, p3));
    }
    l0 += __shfl_xor_sync(0xffffffffu, l0, 1);
    l0 += __shfl_xor_sync(0xffffffffu, l0, 2);
    l1 += __shfl_xor_sync(0xffffffffu, l1, 1);
    l1 += __shfl_xor_sync(0xffffffffu, l1, 2);

    asm volatile("cp.async.wait_group 0;");
    __syncthreads();

    float ov[8][4];
#pragma unroll
    for (int nt = 0; nt < 8; ++nt) {
        ov[nt][0] = 0.f; ov[nt][1] = 0.f; ov[nt][2] = 0.f; ov[nt][3] = 0.f;
    }
#pragma unroll
    for (int kj = 0; kj < 16; ++kj) {
        unsigned a0 = ph[2 * kj][0];
        unsigned a1 = ph[2 * kj][1];
        unsigned a2 = ph[2 * kj + 1][0];
        unsigned a3 = ph[2 * kj + 1][1];
        const int row = 16 * kj + 8 * (tsel & 1) + rr;
#pragma unroll
        for (int ntp = 0; ntp < 4; ++ntp) {
            int ch = 2 * ntp + (tsel >> 1);
            unsigned b0, b1, b2, b3;
            ldsm4t(b0, b1, b2, b3,
                   vsB + (unsigned)(2 * (row * 64 + ((ch ^ (row & 7)) << 3))));
            mma_f16(ov[2 * ntp],     a0, a1, a2, a3, b0, b1);
            mma_f16(ov[2 * ntp + 1], a0, a1, a2, a3, b2, b3);
        }
    }

    float inv0 = 1.f / l0, inv1 = 1.f / l1;
    const int row_lo = tok0 + m0 + g;
#pragma unroll
    for (int nt = 0; nt < 8; ++nt) {
        int col = h * DHEAD + 8 * nt + 2 * tg;
        __half2 h0 = __floats2half2_rn(ov[nt][0] * inv0, ov[nt][1] * inv0);
        __half2 h1 = __floats2half2_rn(ov[nt][2] * inv1, ov[nt][3] * inv1);
        *reinterpret_cast<__half2*>(&o[(size_t)row_lo * HD + col]) = h0;
        *reinterpret_cast<__half2*>(&o[(size_t)(row_lo + 8) * HD + col]) = h1;
    }
}

// ---------------- launch ----------------
extern "C" void kernel_launch(void* const* d_in, const int* in_sizes, int n_in,
                              void* d_out, int out_size)
{
    (void)in_sizes; (void)n_in; (void)out_size;
    const float* x     = (const float*)d_in[0];  // [16384, 1024]
    const float* w_qkv = (const float*)d_in[1];  // [1024, 1536]
    const float* w_out = (const float*)d_in[2];  // [512, 1024]
    const float* b_out = (const float*)d_in[3];  // [1024]
    float*       out   = (float*)d_out;          // [16384, 1024]

    __half *xh, *wqkvT, *woutT, *qkvh, *attnh;
    cudaGetSymbolAddress((void**)&xh,    g_xh);
    cudaGetSymbolAddress((void**)&wqkvT, g_wqkvT);
    cudaGetSymbolAddress((void**)&woutT, g_woutT);
    cudaGetSymbolAddress((void**)&qkvh,  g_qkvh);
    cudaGetSymbolAddress((void**)&attnh, g_attnh);

    cudaFuncSetAttribute((const void*)h16gemm<false, true>,
                         cudaFuncAttributeMaxDynamicSharedMemorySize, HG_SMEM);
    cudaFuncSetAttribute((const void*)h16gemm<true, false>,
                         cudaFuncAttributeMaxDynamicSharedMemorySize, HG_SMEM);
    cudaFuncSetAttribute((const void*)attn_h16_kernel,
                         cudaFuncAttributeMaxDynamicSharedMemorySize, ATTN_SMEM_B);

    // 0) fused prepass: x -> half, w_qkv^T -> half, w_out^T -> half (one launch)
    prepass_kernel<<<PREP_BLOCKS, 256>>>(x, w_qkv, w_out);

    // 1) QKV projection: [16384,1024] @ [1024,1536], half out
    {
        dim3 grid(QKVW / 128, N_TOK / 128);
        h16gemm<false, true><<<grid, 256, HG_SMEM>>>(xh, wqkvT, nullptr, qkvh,
                                                     N_TOK, QKVW, DIM);
    }

    // 2) windowed look-back attention (fp16 mma, fp32 softmax)
    {
        dim3 grid(NWIN, HEADS);
        attn_h16_kernel<<<grid, 256, ATTN_SMEM_B>>>(qkvh, attnh);
    }

    // 3) output projection: [16384,512] @ [512,1024] + bias, fp32 out
    {
        dim3 grid(DIM / 128, N_TOK / 128);
        h16gemm<true, false><<<grid, 256, HG_SMEM>>>(attnh, woutT, b_out, out,
                                                     N_TOK, DIM, HD);
    }
}

// round 16
// speedup vs baseline: 1.1768x; 1.0041x over previous
#include <cuda_runtime.h>
#include <cuda_fp16.h>
#include <cstdint>

// ---------------- problem constants ----------------
#define N_TOK   16384
#define DIM     1024
#define HEADS   8
#define DHEAD   64
#define HD      (HEADS * DHEAD)   // 512
#define QKVW    (3 * HD)          // 1536
#define WSZ     128
#define NWIN    (N_TOK / WSZ)     // 128

// ---------------- scratch ----------------
__device__ __half g_xh[(size_t)N_TOK * DIM];      // x -> half
__device__ __half g_wqkvT[(size_t)QKVW * DIM];    // w_qkv^T half  [1536][1024]
__device__ __half g_woutT[(size_t)DIM * HD];      // w_out^T half  [1024][512]
__device__ __half g_qkvh[(size_t)N_TOK * QKVW];   // GEMM1 out half
__device__ __half g_attnh[(size_t)N_TOK * HD];    // attention out half
__device__ __align__(16) __half g_zero16[8];      // 16B of zeros (cp.async src)

// ---------------- helpers ----------------
__device__ __forceinline__ unsigned h2u(__half2 h) {
    return *reinterpret_cast<unsigned*>(&h);
}

__device__ __forceinline__ void mma_f16(float c[4], unsigned a0, unsigned a1,
                                        unsigned a2, unsigned a3,
                                        unsigned b0, unsigned b1) {
    asm volatile(
        "mma.sync.aligned.m16n8k16.row.col.f32.f16.f16.f32 "
        "{%0,%1,%2,%3}, {%4,%5,%6,%7}, {%8,%9}, {%0,%1,%2,%3};"
        : "+f"(c[0]), "+f"(c[1]), "+f"(c[2]), "+f"(c[3])
        : "r"(a0), "r"(a1), "r"(a2), "r"(a3), "r"(b0), "r"(b1));
}

__device__ __forceinline__ void ldsm4(unsigned& r0, unsigned& r1,
                                      unsigned& r2, unsigned& r3, unsigned addr) {
    asm volatile("ldmatrix.sync.aligned.m8n8.x4.shared.b16 {%0,%1,%2,%3}, [%4];"
                 : "=r"(r0), "=r"(r1), "=r"(r2), "=r"(r3) : "r"(addr));
}

__device__ __forceinline__ void ldsm4t(unsigned& r0, unsigned& r1,
                                       unsigned& r2, unsigned& r3, unsigned addr) {
    asm volatile("ldmatrix.sync.aligned.m8n8.x4.trans.shared.b16 {%0,%1,%2,%3}, [%4];"
                 : "=r"(r0), "=r"(r1), "=r"(r2), "=r"(r3) : "r"(addr));
}

// ---------------- fused prepass: cvt x + transpose both weights ----------------
#define XB  (N_TOK * DIM / 4 / 256)            // 16384 blocks
#define T1X (QKVW / 32)                        // 48
#define T1Y (DIM / 32)                         // 32
#define T2X (DIM / 32)                         // 32
#define T2Y (HD / 32)                          // 16
#define PREP_BLOCKS (XB + T1X * T1Y + T2X * T2Y)

__global__ __launch_bounds__(256)
void prepass_kernel(const float* __restrict__ x, const float* __restrict__ w_qkv,
                    const float* __restrict__ w_out)
{
    int b = blockIdx.x;
    if (b < XB) {
        int i = b * 256 + threadIdx.x;
        float4 v = reinterpret_cast<const float4*>(x)[i];
        __half2* out = reinterpret_cast<__half2*>(g_xh);
        out[2 * i + 0] = __floats2half2_rn(v.x, v.y);
        out[2 * i + 1] = __floats2half2_rn(v.z, v.w);
        return;
    }
    __shared__ float t[32][33];
    const float* in;
    __half* out;
    int R, C, bx, by;
    if (b < XB + T1X * T1Y) {
        int bb = b - XB;
        in = w_qkv; out = g_wqkvT; R = DIM; C = QKVW;
        bx = (bb % T1X) * 32; by = (bb / T1X) * 32;
    } else {
        int bb = b - XB - T1X * T1Y;
        in = w_out; out = g_woutT; R = HD; C = DIM;
        bx = (bb % T2X) * 32; by = (bb / T2X) * 32;
    }
    int tx = threadIdx.x & 31, ty = threadIdx.x >> 5;   // 32 x 8
    int xcol = bx + tx;
#pragma unroll
    for (int i = 0; i < 32; i += 8) {
        int y = by + ty + i;
        t[ty + i][tx] = in[(size_t)y * C + xcol];
    }
    __syncthreads();
    int xo = by + tx;
#pragma unroll
    for (int i = 0; i < 32; i += 8) {
        int yo = bx + ty + i;
        out[(size_t)yo * R + xo] = __float2half_rn(t[tx][ty + i]);
    }
}

// ---------------- FP16 tensor-core GEMM ----------------
// C[M,N] = A[M,K] @ Bt[N,K]^T (+bias). A, Bt half row-major.
// CTA 128x128x64(halves), 4 warps 2x2 (warp tile 64x64), 128 threads,
// 3-stage cp.async (wait_group 1, prefetch distance 2), one barrier per k-tile,
// ldmatrix.x4 loads. smem row r = 64 halves, 16B chunk c at c^(r&7).
// Stage s at byte s*32768; A [0,16384), B [16384,32768).
#define CPA16(dst, src) \
    asm volatile("cp.async.cg.shared.global [%0], [%1], 16;" :: "r"(dst), "l"(src))

#define HSTAGE 16384                       // halves per stage (A 8192 + B 8192)
#define HG_SMEM (3 * HSTAGE * 2)           // 98304 bytes

template <bool WITH_BIAS, bool HALF_OUT>
__global__ __launch_bounds__(128, 2)
void h16gemm(const __half* __restrict__ A, const __half* __restrict__ Bt,
             const float* __restrict__ bias, void* __restrict__ Cout,
             int M, int N, int K)
{
    extern __shared__ __half hsm[];
    const unsigned smBase = (unsigned)__cvta_generic_to_shared(hsm);

    const int tid  = threadIdx.x;
    const int lane = tid & 31;
    const int wid  = tid >> 5;
    const int wm   = wid >> 1;          // 0..1 (64-row slabs)
    const int wn   = wid & 1;           // 0..1 (64-col slabs)
    const int g    = lane >> 2;         // 0..7
    const int tg   = lane & 3;          // 0..3

    const int row0 = blockIdx.y * 128;
    const int col0 = blockIdx.x * 128;
    const int NKT  = K / 64;

    float acc[4][8][4];
#pragma unroll
    for (int mi = 0; mi < 4; ++mi)
#pragma unroll
        for (int ni = 0; ni < 8; ++ni)
#pragma unroll
            for (int r = 0; r < 4; ++r) acc[mi][ni][r] = 0.f;

    auto issue = [&](int kt, int s) {
        const unsigned sb = smBase + (unsigned)s * (HSTAGE * 2);
#pragma unroll
        for (int p = 0; p < 8; ++p) {       // A: 1024 chunks / 128 thr
            int idx = p * 128 + tid;
            int r = idx >> 3, c = idx & 7;
            CPA16(sb + (unsigned)(r * 128 + ((c ^ (r & 7)) * 16)),
                  A + (size_t)(row0 + r) * K + kt * 64 + c * 8);
        }
#pragma unroll
        for (int p = 0; p < 8; ++p) {       // B: 1024 chunks
            int idx = p * 128 + tid;
            int r = idx >> 3, c = idx & 7;
            CPA16(sb + 16384u + (unsigned)(r * 128 + ((c ^ (r & 7)) * 16)),
                  Bt + (size_t)(col0 + r) * K + kt * 64 + c * 8);
        }
        asm volatile("cp.async.commit_group;");
    };

    issue(0, 0);
    issue(1, 1);

    // ldmatrix lane decomposition
    const int lr  = lane & 15;
    const int lc  = lane >> 4;
    const int bn8 = 8 * (lane >> 4) + (lane & 7);
    const int bcp = (lane >> 3) & 1;

    for (int kt = 0; kt < NKT; ++kt) {
        const int s = kt % 3;
        if (kt + 1 < NKT) asm volatile("cp.async.wait_group 1;");
        else              asm volatile("cp.async.wait_group 0;");
        __syncthreads();   // publishes group kt; protects stage (kt+2)%3
        if (kt + 2 < NKT) issue(kt + 2, (kt + 2) % 3);

        const unsigned sA = smBase + (unsigned)s * (HSTAGE * 2);
        const unsigned sB = sA + 16384u;

#pragma unroll
        for (int ks = 0; ks < 4; ++ks) {
            unsigned a[4][4];
#pragma unroll
            for (int mi = 0; mi < 4; ++mi) {
                int m = wm * 64 + mi * 16 + lr;
                int c = 2 * ks + lc;
                ldsm4(a[mi][0], a[mi][1], a[mi][2], a[mi][3],
                      sA + (unsigned)(2 * (m * 64 + ((c ^ (m & 7)) << 3))));
            }
            unsigned b[8][2];
#pragma unroll
            for (int blk = 0; blk < 4; ++blk) {
                int n = wn * 64 + 16 * blk + bn8;
                int c = 2 * ks + bcp;
                ldsm4(b[2 * blk][0], b[2 * blk][1], b[2 * blk + 1][0], b[2 * blk + 1][1],
                      sB + (unsigned)(2 * (n * 64 + ((c ^ (n & 7)) << 3))));
            }
#pragma unroll
            for (int mi = 0; mi < 4; ++mi)
#pragma unroll
                for (int ni = 0; ni < 8; ++ni)
                    mma_f16(acc[mi][ni], a[mi][0], a[mi][1], a[mi][2], a[mi][3],
                            b[ni][0], b[ni][1]);
        }
        // no loop-end barrier (top barrier of next iter covers the hazard)
    }

    // epilogue
#pragma unroll
    for (int ni = 0; ni < 8; ++ni) {
        int col = col0 + wn * 64 + ni * 8 + 2 * tg;
        float bx = 0.f, by = 0.f;
        if (WITH_BIAS) { bx = bias[col]; by = bias[col + 1]; }
#pragma unroll
        for (int mi = 0; mi < 4; ++mi) {
            int row = row0 + wm * 64 + mi * 16 + g;
            if (HALF_OUT) {
                __half* C = (__half*)Cout;
                __half2 h0 = __floats2half2_rn(acc[mi][ni][0], acc[mi][ni][1]);
                __half2 h1 = __floats2half2_rn(acc[mi][ni][2], acc[mi][ni][3]);
                *reinterpret_cast<__half2*>(&C[(size_t)row * N + col]) = h0;
                *reinterpret_cast<__half2*>(&C[(size_t)(row + 8) * N + col]) = h1;
            } else {
                float* C = (float*)Cout;
                float2 v0 = make_float2(acc[mi][ni][0] + bx, acc[mi][ni][1] + by);
                float2 v1 = make_float2(acc[mi][ni][2] + bx, acc[mi][ni][3] + by);
                *reinterpret_cast<float2*>(&C[(size_t)row * N + col]) = v0;
                *reinterpret_cast<float2*>(&C[(size_t)(row + 8) * N + col]) = v1;
            }
        }
    }
}

// ---------------- FP16 tensor-core attention (round-15, passed) ----------------
#define ATTN_SMEM_B (40960 * 2)            // 81920 bytes

__global__ __launch_bounds__(256)
void attn_h16_kernel(const __half* __restrict__ qkv, __half* __restrict__ o)
{
    extern __shared__ __half hs[];
    const unsigned smB = (unsigned)__cvta_generic_to_shared(hs);
    const unsigned qsB = smB;
    const unsigned ksB = smB + 8192u * 2u;
    const unsigned vsB = smB + 24576u * 2u;

    const int w    = blockIdx.x;
    const int h    = blockIdx.y;
    const int tid  = threadIdx.x;
    const int lane = tid & 31;
    const int wq   = tid >> 5;
    const int g    = lane >> 2;
    const int tg   = lane & 3;
    const int m0   = wq * 16;
    const int tok0 = w * WSZ;

    // ---- group A: Q + K ----
#pragma unroll
    for (int p = 0; p < 4; ++p) {
        int idx = p * 256 + tid;
        int row = idx >> 3, c = idx & 7;
        CPA16(qsB + (unsigned)(row * 128 + ((c ^ (row & 7)) * 16)),
              qkv + (size_t)(tok0 + row) * QKVW + h * DHEAD + c * 8);
    }
#pragma unroll
    for (int p = 0; p < 8; ++p) {
        int idx = p * 256 + tid;
        int j = idx >> 3, c = idx & 7;
        const __half* src = (w == 0 && j < WSZ)
            ? g_zero16
            : qkv + (size_t)(tok0 - WSZ + j) * QKVW + HD + h * DHEAD + c * 8;
        CPA16(ksB + (unsigned)(j * 128 + ((c ^ (j & 7)) * 16)), src);
    }
    asm volatile("cp.async.commit_group;");

    // ---- group B: V ----
#pragma unroll
    for (int p = 0; p < 8; ++p) {
        int idx = p * 256 + tid;
        int j = idx >> 3, c = idx & 7;
        const __half* src = (w == 0 && j < WSZ)
            ? g_zero16
            : qkv + (size_t)(tok0 - WSZ + j) * QKVW + 2 * HD + h * DHEAD + c * 8;
        CPA16(vsB + (unsigned)(j * 128 + ((c ^ (j & 7)) * 16)), src);
    }
    asm volatile("cp.async.commit_group;");

    asm volatile("cp.async.wait_group 1;");
    __syncthreads();

    const int lr  = lane & 15;
    const int lc  = lane >> 4;
    const int bn8 = 8 * (lane >> 4) + (lane & 7);
    const int bcp = (lane >> 3) & 1;
    const int rr   = lane & 7;
    const int tsel = lane >> 3;

    unsigned qa[4][4];
#pragma unroll
    for (int ks = 0; ks < 4; ++ks) {
        int m = m0 + lr;
        int c = 2 * ks + lc;
        ldsm4(qa[ks][0], qa[ks][1], qa[ks][2], qa[ks][3],
              qsB + (unsigned)(2 * (m * 64 + ((c ^ (m & 7)) << 3))));
    }

    float s[32][4];
#pragma unroll
    for (int nt = 0; nt < 32; ++nt) {
        s[nt][0] = 0.f; s[nt][1] = 0.f; s[nt][2] = 0.f; s[nt][3] = 0.f;
    }
#pragma unroll
    for (int ntp = 0; ntp < 16; ++ntp) {
        const int jb = 16 * ntp + bn8;
#pragma unroll
        for (int ks = 0; ks < 4; ++ks) {
            int c = 2 * ks + bcp;
            unsigned b0, b1, b2, b3;
            ldsm4(b0, b1, b2, b3,
                  ksB + (unsigned)(2 * (jb * 64 + ((c ^ (jb & 7)) << 3))));
            mma_f16(s[2 * ntp],     qa[ks][0], qa[ks][1], qa[ks][2], qa[ks][3], b0, b1);
            mma_f16(s[2 * ntp + 1], qa[ks][0], qa[ks][1], qa[ks][2], qa[ks][3], b2, b3);
        }
    }

    const int i_lo = m0 + g, i_hi = i_lo + 8;
    float mx0 = -3.0e38f, mx1 = -3.0e38f;
#pragma unroll
    for (int nt = 0; nt < 32; ++nt) {
        int j0 = 8 * nt + 2 * tg, j1 = j0 + 1;
        s[nt][0] = (j0 > i_lo + WSZ) ? -1e10f : s[nt][0] * 0.125f;
        s[nt][1] = (j1 > i_lo + WSZ) ? -1e10f : s[nt][1] * 0.125f;
        s[nt][2] = (j0 > i_hi + WSZ) ? -1e10f : s[nt][2] * 0.125f;
        s[nt][3] = (j1 > i_hi + WSZ) ? -1e10f : s[nt][3] * 0.125f;
        mx0 = fmaxf(mx0, fmaxf(s[nt][0], s[nt][1]));
        mx1 = fmaxf(mx1, fmaxf(s[nt][2], s[nt][3]));
    }
    mx0 = fmaxf(mx0, __shfl_xor_sync(0xffffffffu, mx0, 1));
    mx0 = fmaxf(mx0, __shfl_xor_sync(0xffffffffu, mx0, 2));
    mx1 = fmaxf(mx1, __shfl_xor_sync(0xffffffffu, mx1, 1));
    mx1 = fmaxf(mx1, __shfl_xor_sync(0xffffffffu, mx1, 2));

    float l0 = 0.f, l1 = 0.f;
    unsigned ph[32][2];
#pragma unroll
    for (int nt = 0; nt < 32; ++nt) {
        float p0 = __expf(s[nt][0] - mx0);
        float p1 = __expf(s[nt][1] - mx0);
        float p2 = __expf(s[nt][2] - mx1);
        float p3 = __expf(s[nt][3] - mx1);
        l0 += p0 + p1;
        l1 += p2 + p3;
        ph[nt][0] = h2u(__floats2half2_rn(p0, p1));
        ph[nt][1] = h2u(__floats2half2_rn(p2, p3));
    }
    l0 += __shfl_xor_sync(0xffffffffu, l0, 1);
    l0 += __shfl_xor_sync(0xffffffffu, l0, 2);
    l1 += __shfl_xor_sync(0xffffffffu, l1, 1);
    l1 += __shfl_xor_sync(0xffffffffu, l1, 2);

    asm volatile("cp.async.wait_group 0;");
    __syncthreads();

    float ov[8][4];
#pragma unroll
    for (int nt = 0; nt < 8; ++nt) {
        ov[nt][0] = 0.f; ov[nt][1] = 0.f; ov[nt][2] = 0.f; ov[nt][3] = 0.f;
    }
#pragma unroll
    for (int kj = 0; kj < 16; ++kj) {
        unsigned a0 = ph[2 * kj][0];
        unsigned a1 = ph[2 * kj][1];
        unsigned a2 = ph[2 * kj + 1][0];
        unsigned a3 = ph[2 * kj + 1][1];
        const int row = 16 * kj + 8 * (tsel & 1) + rr;
#pragma unroll
        for (int ntp = 0; ntp < 4; ++ntp) {
            int ch = 2 * ntp + (tsel >> 1);
            unsigned b0, b1, b2, b3;
            ldsm4t(b0, b1, b2, b3,
                   vsB + (unsigned)(2 * (row * 64 + ((ch ^ (row & 7)) << 3))));
            mma_f16(ov[2 * ntp],     a0, a1, a2, a3, b0, b1);
            mma_f16(ov[2 * ntp + 1], a0, a1, a2, a3, b2, b3);
        }
    }

    float inv0 = 1.f / l0, inv1 = 1.f / l1;
    const int row_lo = tok0 + m0 + g;
#pragma unroll
    for (int nt = 0; nt < 8; ++nt) {
        int col = h * DHEAD + 8 * nt + 2 * tg;
        __half2 h0 = __floats2half2_rn(ov[nt][0] * inv0, ov[nt][1] * inv0);
        __half2 h1 = __floats2half2_rn(ov[nt][2] * inv1, ov[nt][3] * inv1);
        *reinterpret_cast<__half2*>(&o[(size_t)row_lo * HD + col]) = h0;
        *reinterpret_cast<__half2*>(&o[(size_t)(row_lo + 8) * HD + col]) = h1;
    }
}

// ---------------- launch ----------------
extern "C" void kernel_launch(void* const* d_in, const int* in_sizes, int n_in,
                              void* d_out, int out_size)
{
    (void)in_sizes; (void)n_in; (void)out_size;
    const float* x     = (const float*)d_in[0];  // [16384, 1024]
    const float* w_qkv = (const float*)d_in[1];  // [1024, 1536]
    const float* w_out = (const float*)d_in[2];  // [512, 1024]
    const float* b_out = (const float*)d_in[3];  // [1024]
    float*       out   = (float*)d_out;          // [16384, 1024]

    __half *xh, *wqkvT, *woutT, *qkvh, *attnh;
    cudaGetSymbolAddress((void**)&xh,    g_xh);
    cudaGetSymbolAddress((void**)&wqkvT, g_wqkvT);
    cudaGetSymbolAddress((void**)&woutT, g_woutT);
    cudaGetSymbolAddress((void**)&qkvh,  g_qkvh);
    cudaGetSymbolAddress((void**)&attnh, g_attnh);

    cudaFuncSetAttribute((const void*)h16gemm<false, true>,
                         cudaFuncAttributeMaxDynamicSharedMemorySize, HG_SMEM);
    cudaFuncSetAttribute((const void*)h16gemm<true, false>,
                         cudaFuncAttributeMaxDynamicSharedMemorySize, HG_SMEM);
    cudaFuncSetAttribute((const void*)attn_h16_kernel,
                         cudaFuncAttributeMaxDynamicSharedMemorySize, ATTN_SMEM_B);

    // 0) fused prepass: x -> half, w_qkv^T -> half, w_out^T -> half
    prepass_kernel<<<PREP_BLOCKS, 256>>>(x, w_qkv, w_out);

    // 1) QKV projection: [16384,1024] @ [1024,1536], half out
    {
        dim3 grid(QKVW / 128, N_TOK / 128);
        h16gemm<false, true><<<grid, 128, HG_SMEM>>>(xh, wqkvT, nullptr, qkvh,
                                                     N_TOK, QKVW, DIM);
    }

    // 2) windowed look-back attention (fp16 mma, fp32 softmax)
    {
        dim3 grid(NWIN, HEADS);
        attn_h16_kernel<<<grid, 256, ATTN_SMEM_B>>>(qkvh, attnh);
    }

    // 3) output projection: [16384,512] @ [512,1024] + bias, fp32 out
    {
        dim3 grid(DIM / 128, N_TOK / 128);
        h16gemm<true, false><<<grid, 128, HG_SMEM>>>(attnh, woutT, b_out, out,
                                                     N_TOK, DIM, HD);
    }
}

// round 17
// speedup vs baseline: 1.1790x; 1.0019x over previous
#include <cuda_runtime.h>
#include <cuda_fp16.h>
#include <cstdint>

// ---------------- problem constants ----------------
#define N_TOK   16384
#define DIM     1024
#define HEADS   8
#define DHEAD   64
#define HD      (HEADS * DHEAD)   // 512
#define QKVW    (3 * HD)          // 1536
#define WSZ     128
#define NWIN    (N_TOK / WSZ)     // 128

// ---------------- scratch ----------------
__device__ __half g_xh[(size_t)N_TOK * DIM];      // x -> half
__device__ __half g_wqkvT[(size_t)QKVW * DIM];    // w_qkv^T half  [1536][1024]
__device__ __half g_woutT[(size_t)DIM * HD];      // w_out^T half  [1024][512]
__device__ __half g_qkvh[(size_t)N_TOK * QKVW];   // GEMM1 out half
__device__ __half g_attnh[(size_t)N_TOK * HD];    // attention out half
__device__ __align__(16) __half g_zero16[8];      // 16B of zeros (cp.async src)

// ---------------- helpers ----------------
__device__ __forceinline__ unsigned h2u(__half2 h) {
    return *reinterpret_cast<unsigned*>(&h);
}

__device__ __forceinline__ void mma_f16(float c[4], unsigned a0, unsigned a1,
                                        unsigned a2, unsigned a3,
                                        unsigned b0, unsigned b1) {
    asm volatile(
        "mma.sync.aligned.m16n8k16.row.col.f32.f16.f16.f32 "
        "{%0,%1,%2,%3}, {%4,%5,%6,%7}, {%8,%9}, {%0,%1,%2,%3};"
        : "+f"(c[0]), "+f"(c[1]), "+f"(c[2]), "+f"(c[3])
        : "r"(a0), "r"(a1), "r"(a2), "r"(a3), "r"(b0), "r"(b1));
}

__device__ __forceinline__ void ldsm4(unsigned& r0, unsigned& r1,
                                      unsigned& r2, unsigned& r3, unsigned addr) {
    asm volatile("ldmatrix.sync.aligned.m8n8.x4.shared.b16 {%0,%1,%2,%3}, [%4];"
                 : "=r"(r0), "=r"(r1), "=r"(r2), "=r"(r3) : "r"(addr));
}

__device__ __forceinline__ void ldsm4t(unsigned& r0, unsigned& r1,
                                       unsigned& r2, unsigned& r3, unsigned addr) {
    asm volatile("ldmatrix.sync.aligned.m8n8.x4.trans.shared.b16 {%0,%1,%2,%3}, [%4];"
                 : "=r"(r0), "=r"(r1), "=r"(r2), "=r"(r3) : "r"(addr));
}

// ---------------- fused prepass: cvt x + transpose both weights ----------------
#define XB  (N_TOK * DIM / 4 / 256)            // 16384 blocks
#define T1X (QKVW / 32)                        // 48
#define T1Y (DIM / 32)                         // 32
#define T2X (DIM / 32)                         // 32
#define T2Y (HD / 32)                          // 16
#define PREP_BLOCKS (XB + T1X * T1Y + T2X * T2Y)

__global__ __launch_bounds__(256)
void prepass_kernel(const float* __restrict__ x, const float* __restrict__ w_qkv,
                    const float* __restrict__ w_out)
{
    int b = blockIdx.x;
    if (b < XB) {
        int i = b * 256 + threadIdx.x;
        float4 v = reinterpret_cast<const float4*>(x)[i];
        __half2* out = reinterpret_cast<__half2*>(g_xh);
        out[2 * i + 0] = __floats2half2_rn(v.x, v.y);
        out[2 * i + 1] = __floats2half2_rn(v.z, v.w);
        return;
    }
    __shared__ float t[32][33];
    const float* in;
    __half* out;
    int R, C, bx, by;
    if (b < XB + T1X * T1Y) {
        int bb = b - XB;
        in = w_qkv; out = g_wqkvT; R = DIM; C = QKVW;
        bx = (bb % T1X) * 32; by = (bb / T1X) * 32;
    } else {
        int bb = b - XB - T1X * T1Y;
        in = w_out; out = g_woutT; R = HD; C = DIM;
        bx = (bb % T2X) * 32; by = (bb / T2X) * 32;
    }
    int tx = threadIdx.x & 31, ty = threadIdx.x >> 5;
    int xcol = bx + tx;
#pragma unroll
    for (int i = 0; i < 32; i += 8) {
        int y = by + ty + i;
        t[ty + i][tx] = in[(size_t)y * C + xcol];
    }
    __syncthreads();
    int xo = by + tx;
#pragma unroll
    for (int i = 0; i < 32; i += 8) {
        int yo = bx + ty + i;
        out[(size_t)yo * R + xo] = __float2half_rn(t[tx][ty + i]);
    }
}

// ---------------- FP16 tensor-core GEMM (round-16 config, frozen) ----------------
// CTA 128x128x64(halves), 4 warps 2x2 (warp tile 64x64), 128 threads,
// 3-stage cp.async (wait_group 1, prefetch 2), one barrier per k-tile, ldmatrix.x4.
#define CPA16(dst, src) \
    asm volatile("cp.async.cg.shared.global [%0], [%1], 16;" :: "r"(dst), "l"(src))

#define HSTAGE 16384
#define HG_SMEM (3 * HSTAGE * 2)           // 98304 bytes

template <bool WITH_BIAS, bool HALF_OUT>
__global__ __launch_bounds__(128, 2)
void h16gemm(const __half* __restrict__ A, const __half* __restrict__ Bt,
             const float* __restrict__ bias, void* __restrict__ Cout,
             int M, int N, int K)
{
    extern __shared__ __half hsm[];
    const unsigned smBase = (unsigned)__cvta_generic_to_shared(hsm);

    const int tid  = threadIdx.x;
    const int lane = tid & 31;
    const int wid  = tid >> 5;
    const int wm   = wid >> 1;
    const int wn   = wid & 1;
    const int g    = lane >> 2;
    const int tg   = lane & 3;

    const int row0 = blockIdx.y * 128;
    const int col0 = blockIdx.x * 128;
    const int NKT  = K / 64;

    float acc[4][8][4];
#pragma unroll
    for (int mi = 0; mi < 4; ++mi)
#pragma unroll
        for (int ni = 0; ni < 8; ++ni)
#pragma unroll
            for (int r = 0; r < 4; ++r) acc[mi][ni][r] = 0.f;

    auto issue = [&](int kt, int s) {
        const unsigned sb = smBase + (unsigned)s * (HSTAGE * 2);
#pragma unroll
        for (int p = 0; p < 8; ++p) {
            int idx = p * 128 + tid;
            int r = idx >> 3, c = idx & 7;
            CPA16(sb + (unsigned)(r * 128 + ((c ^ (r & 7)) * 16)),
                  A + (size_t)(row0 + r) * K + kt * 64 + c * 8);
        }
#pragma unroll
        for (int p = 0; p < 8; ++p) {
            int idx = p * 128 + tid;
            int r = idx >> 3, c = idx & 7;
            CPA16(sb + 16384u + (unsigned)(r * 128 + ((c ^ (r & 7)) * 16)),
                  Bt + (size_t)(col0 + r) * K + kt * 64 + c * 8);
        }
        asm volatile("cp.async.commit_group;");
    };

    issue(0, 0);
    issue(1, 1);

    const int lr  = lane & 15;
    const int lc  = lane >> 4;
    const int bn8 = 8 * (lane >> 4) + (lane & 7);
    const int bcp = (lane >> 3) & 1;

    for (int kt = 0; kt < NKT; ++kt) {
        const int s = kt % 3;
        if (kt + 1 < NKT) asm volatile("cp.async.wait_group 1;");
        else              asm volatile("cp.async.wait_group 0;");
        __syncthreads();
        if (kt + 2 < NKT) issue(kt + 2, (kt + 2) % 3);

        const unsigned sA = smBase + (unsigned)s * (HSTAGE * 2);
        const unsigned sB = sA + 16384u;

#pragma unroll
        for (int ks = 0; ks < 4; ++ks) {
            unsigned a[4][4];
#pragma unroll
            for (int mi = 0; mi < 4; ++mi) {
                int m = wm * 64 + mi * 16 + lr;
                int c = 2 * ks + lc;
                ldsm4(a[mi][0], a[mi][1], a[mi][2], a[mi][3],
                      sA + (unsigned)(2 * (m * 64 + ((c ^ (m & 7)) << 3))));
            }
            unsigned b[8][2];
#pragma unroll
            for (int blk = 0; blk < 4; ++blk) {
                int n = wn * 64 + 16 * blk + bn8;
                int c = 2 * ks + bcp;
                ldsm4(b[2 * blk][0], b[2 * blk][1], b[2 * blk + 1][0], b[2 * blk + 1][1],
                      sB + (unsigned)(2 * (n * 64 + ((c ^ (n & 7)) << 3))));
            }
#pragma unroll
            for (int mi = 0; mi < 4; ++mi)
#pragma unroll
                for (int ni = 0; ni < 8; ++ni)
                    mma_f16(acc[mi][ni], a[mi][0], a[mi][1], a[mi][2], a[mi][3],
                            b[ni][0], b[ni][1]);
        }
    }

#pragma unroll
    for (int ni = 0; ni < 8; ++ni) {
        int col = col0 + wn * 64 + ni * 8 + 2 * tg;
        float bx = 0.f, by = 0.f;
        if (WITH_BIAS) { bx = bias[col]; by = bias[col + 1]; }
#pragma unroll
        for (int mi = 0; mi < 4; ++mi) {
            int row = row0 + wm * 64 + mi * 16 + g;
            if (HALF_OUT) {
                __half* C = (__half*)Cout;
                __half2 h0 = __floats2half2_rn(acc[mi][ni][0], acc[mi][ni][1]);
                __half2 h1 = __floats2half2_rn(acc[mi][ni][2], acc[mi][ni][3]);
                *reinterpret_cast<__half2*>(&C[(size_t)row * N + col]) = h0;
                *reinterpret_cast<__half2*>(&C[(size_t)(row + 8) * N + col]) = h1;
            } else {
                float* C = (float*)Cout;
                float2 v0 = make_float2(acc[mi][ni][0] + bx, acc[mi][ni][1] + by);
                float2 v1 = make_float2(acc[mi][ni][2] + bx, acc[mi][ni][3] + by);
                *reinterpret_cast<float2*>(&C[(size_t)row * N + col]) = v0;
                *reinterpret_cast<float2*>(&C[(size_t)(row + 8) * N + col]) = v1;
            }
        }
    }
}

// ---------------- FP16 tensor-core attention, split-KV (2 chunks of 128) ----------------
// One CTA per (window, head), 256 threads, 2 CTAs/SM (regs ~125 via chunking).
// smem: qs [128][64] @0, ks [256][64] @16KB, vs [256][64] @48KB, all swizzled.
// Online softmax across the 2 chunks; P stored in place of S (half2 puns).
#define ATTN_SMEM_B (40960 * 2)            // 81920 bytes

__global__ __launch_bounds__(256, 2)
void attn_h16_kernel(const __half* __restrict__ qkv, __half* __restrict__ o)
{
    extern __shared__ __half hs[];
    const unsigned smB = (unsigned)__cvta_generic_to_shared(hs);
    const unsigned qsB = smB;
    const unsigned ksB = smB + 8192u * 2u;
    const unsigned vsB = smB + 24576u * 2u;

    const int w    = blockIdx.x;
    const int h    = blockIdx.y;
    const int tid  = threadIdx.x;
    const int lane = tid & 31;
    const int wq   = tid >> 5;
    const int g    = lane >> 2;
    const int tg   = lane & 3;
    const int m0   = wq * 16;
    const int tok0 = w * WSZ;

    // ---- group A: Q + K ----
#pragma unroll
    for (int p = 0; p < 4; ++p) {
        int idx = p * 256 + tid;
        int row = idx >> 3, c = idx & 7;
        CPA16(qsB + (unsigned)(row * 128 + ((c ^ (row & 7)) * 16)),
              qkv + (size_t)(tok0 + row) * QKVW + h * DHEAD + c * 8);
    }
#pragma unroll
    for (int p = 0; p < 8; ++p) {
        int idx = p * 256 + tid;
        int j = idx >> 3, c = idx & 7;
        const __half* src = (w == 0 && j < WSZ)
            ? g_zero16
            : qkv + (size_t)(tok0 - WSZ + j) * QKVW + HD + h * DHEAD + c * 8;
        CPA16(ksB + (unsigned)(j * 128 + ((c ^ (j & 7)) * 16)), src);
    }
    asm volatile("cp.async.commit_group;");

    // ---- group B: V ----
#pragma unroll
    for (int p = 0; p < 8; ++p) {
        int idx = p * 256 + tid;
        int j = idx >> 3, c = idx & 7;
        const __half* src = (w == 0 && j < WSZ)
            ? g_zero16
            : qkv + (size_t)(tok0 - WSZ + j) * QKVW + 2 * HD + h * DHEAD + c * 8;
        CPA16(vsB + (unsigned)(j * 128 + ((c ^ (j & 7)) * 16)), src);
    }
    asm volatile("cp.async.commit_group;");

    asm volatile("cp.async.wait_group 1;");   // Q + K ready
    __syncthreads();

    const int lr  = lane & 15;
    const int lc  = lane >> 4;
    const int bn8 = 8 * (lane >> 4) + (lane & 7);
    const int bcp = (lane >> 3) & 1;
    const int rr   = lane & 7;
    const int tsel = lane >> 3;

    const int i_lo = m0 + g, i_hi = i_lo + 8;

    float m0r = -3.0e38f, m1r = -3.0e38f, l0 = 0.f, l1 = 0.f;
    float ov[8][4];
#pragma unroll
    for (int nt = 0; nt < 8; ++nt) {
        ov[nt][0] = 0.f; ov[nt][1] = 0.f; ov[nt][2] = 0.f; ov[nt][3] = 0.f;
    }

#pragma unroll 1
    for (int c2 = 0; c2 < 2; ++c2) {
        const int jbase = 128 * c2;

        // ---- S chunk = Q @ K^T over keys [jbase, jbase+128) ----
        float s[16][4];
#pragma unroll
        for (int nt = 0; nt < 16; ++nt) {
            s[nt][0] = 0.f; s[nt][1] = 0.f; s[nt][2] = 0.f; s[nt][3] = 0.f;
        }
#pragma unroll
        for (int ks = 0; ks < 4; ++ks) {
            unsigned qa0, qa1, qa2, qa3;
            {
                int m = m0 + lr;
                int c = 2 * ks + lc;
                ldsm4(qa0, qa1, qa2, qa3,
                      qsB + (unsigned)(2 * (m * 64 + ((c ^ (m & 7)) << 3))));
            }
#pragma unroll
            for (int ntp = 0; ntp < 8; ++ntp) {
                int jb = jbase + 16 * ntp + bn8;
                int c = 2 * ks + bcp;
                unsigned b0, b1, b2, b3;
                ldsm4(b0, b1, b2, b3,
                      ksB + (unsigned)(2 * (jb * 64 + ((c ^ (jb & 7)) << 3))));
                mma_f16(s[2 * ntp],     qa0, qa1, qa2, qa3, b0, b1);
                mma_f16(s[2 * ntp + 1], qa0, qa1, qa2, qa3, b2, b3);
            }
        }

        // ---- scale + mask + chunk max ----
        float cx0 = -3.0e38f, cx1 = -3.0e38f;
#pragma unroll
        for (int nt = 0; nt < 16; ++nt) {
            int j0 = jbase + 8 * nt + 2 * tg, j1 = j0 + 1;
            s[nt][0] = (j0 > i_lo + WSZ) ? -1e10f : s[nt][0] * 0.125f;
            s[nt][1] = (j1 > i_lo + WSZ) ? -1e10f : s[nt][1] * 0.125f;
            s[nt][2] = (j0 > i_hi + WSZ) ? -1e10f : s[nt][2] * 0.125f;
            s[nt][3] = (j1 > i_hi + WSZ) ? -1e10f : s[nt][3] * 0.125f;
            cx0 = fmaxf(cx0, fmaxf(s[nt][0], s[nt][1]));
            cx1 = fmaxf(cx1, fmaxf(s[nt][2], s[nt][3]));
        }
        cx0 = fmaxf(cx0, __shfl_xor_sync(0xffffffffu, cx0, 1));
        cx0 = fmaxf(cx0, __shfl_xor_sync(0xffffffffu, cx0, 2));
        cx1 = fmaxf(cx1, __shfl_xor_sync(0xffffffffu, cx1, 1));
        cx1 = fmaxf(cx1, __shfl_xor_sync(0xffffffffu, cx1, 2));

        // ---- online rescale ----
        float mn0 = fmaxf(m0r, cx0), mn1 = fmaxf(m1r, cx1);
        float f0 = __expf(m0r - mn0), f1 = __expf(m1r - mn1);  // chunk0: exp(-inf)=0
        l0 *= f0; l1 *= f1;
#pragma unroll
        for (int nt = 0; nt < 8; ++nt) {
            ov[nt][0] *= f0; ov[nt][1] *= f0;
            ov[nt][2] *= f1; ov[nt][3] *= f1;
        }
        m0r = mn0; m1r = mn1;

        // ---- P = exp(S - m), stored in place as half2 puns ----
        float cl0 = 0.f, cl1 = 0.f;
#pragma unroll
        for (int nt = 0; nt < 16; ++nt) {
            float p0 = __expf(s[nt][0] - mn0);
            float p1 = __expf(s[nt][1] - mn0);
            float p2 = __expf(s[nt][2] - mn1);
            float p3 = __expf(s[nt][3] - mn1);
            cl0 += p0 + p1;
            cl1 += p2 + p3;
            s[nt][0] = __uint_as_float(h2u(__floats2half2_rn(p0, p1)));
            s[nt][1] = __uint_as_float(h2u(__floats2half2_rn(p2, p3)));
        }
        cl0 += __shfl_xor_sync(0xffffffffu, cl0, 1);
        cl0 += __shfl_xor_sync(0xffffffffu, cl0, 2);
        cl1 += __shfl_xor_sync(0xffffffffu, cl1, 1);
        cl1 += __shfl_xor_sync(0xffffffffu, cl1, 2);
        l0 += cl0; l1 += cl1;

        if (c2 == 0) {                         // V ready before first PV
            asm volatile("cp.async.wait_group 0;");
            __syncthreads();
        }

        // ---- PV chunk: O += P @ V[jbase:jbase+128] ----
#pragma unroll
        for (int kj = 0; kj < 8; ++kj) {
            unsigned a0 = __float_as_uint(s[2 * kj][0]);
            unsigned a1 = __float_as_uint(s[2 * kj][1]);
            unsigned a2 = __float_as_uint(s[2 * kj + 1][0]);
            unsigned a3 = __float_as_uint(s[2 * kj + 1][1]);
            const int row = jbase + 16 * kj + 8 * (tsel & 1) + rr;
#pragma unroll
            for (int ntp = 0; ntp < 4; ++ntp) {
                int ch = 2 * ntp + (tsel >> 1);
                unsigned b0, b1, b2, b3;
                ldsm4t(b0, b1, b2, b3,
                       vsB + (unsigned)(2 * (row * 64 + ((ch ^ (row & 7)) << 3))));
                mma_f16(ov[2 * ntp],     a0, a1, a2, a3, b0, b1);
                mma_f16(ov[2 * ntp + 1], a0, a1, a2, a3, b2, b3);
            }
        }
    }

    // ---- normalize + write half ----
    float inv0 = 1.f / l0, inv1 = 1.f / l1;
    const int row_lo = tok0 + m0 + g;
#pragma unroll
    for (int nt = 0; nt < 8; ++nt) {
        int col = h * DHEAD + 8 * nt + 2 * tg;
        __half2 h0 = __floats2half2_rn(ov[nt][0] * inv0, ov[nt][1] * inv0);
        __half2 h1 = __floats2half2_rn(ov[nt][2] * inv1, ov[nt][3] * inv1);
        *reinterpret_cast<__half2*>(&o[(size_t)row_lo * HD + col]) = h0;
        *reinterpret_cast<__half2*>(&o[(size_t)(row_lo + 8) * HD + col]) = h1;
    }
}

// ---------------- launch ----------------
extern "C" void kernel_launch(void* const* d_in, const int* in_sizes, int n_in,
                              void* d_out, int out_size)
{
    (void)in_sizes; (void)n_in; (void)out_size;
    const float* x     = (const float*)d_in[0];  // [16384, 1024]
    const float* w_qkv = (const float*)d_in[1];  // [1024, 1536]
    const float* w_out = (const float*)d_in[2];  // [512, 1024]
    const float* b_out = (const float*)d_in[3];  // [1024]
    float*       out   = (float*)d_out;          // [16384, 1024]

    __half *xh, *wqkvT, *woutT, *qkvh, *attnh;
    cudaGetSymbolAddress((void**)&xh,    g_xh);
    cudaGetSymbolAddress((void**)&wqkvT, g_wqkvT);
    cudaGetSymbolAddress((void**)&woutT, g_woutT);
    cudaGetSymbolAddress((void**)&qkvh,  g_qkvh);
    cudaGetSymbolAddress((void**)&attnh, g_attnh);

    cudaFuncSetAttribute((const void*)h16gemm<false, true>,
                         cudaFuncAttributeMaxDynamicSharedMemorySize, HG_SMEM);
    cudaFuncSetAttribute((const void*)h16gemm<true, false>,
                         cudaFuncAttributeMaxDynamicSharedMemorySize, HG_SMEM);
    cudaFuncSetAttribute((const void*)attn_h16_kernel,
                         cudaFuncAttributeMaxDynamicSharedMemorySize, ATTN_SMEM_B);

    // 0) fused prepass: x -> half, w_qkv^T -> half, w_out^T -> half
    prepass_kernel<<<PREP_BLOCKS, 256>>>(x, w_qkv, w_out);

    // 1) QKV projection: [16384,1024] @ [1024,1536], half out
    {
        dim3 grid(QKVW / 128, N_TOK / 128);
        h16gemm<false, true><<<grid, 128, HG_SMEM>>>(xh, wqkvT, nullptr, qkvh,
                                                     N_TOK, QKVW, DIM);
    }

    // 2) windowed look-back attention (fp16 mma, split-KV online softmax)
    {
        dim3 grid(NWIN, HEADS);
        attn_h16_kernel<<<grid, 256, ATTN_SMEM_B>>>(qkvh, attnh);
    }

    // 3) output projection: [16384,512] @ [512,1024] + bias, fp32 out
    {
        dim3 grid(DIM / 128, N_TOK / 128);
        h16gemm<true, false><<<grid, 128, HG_SMEM>>>(attnh, woutT, b_out, out,
                                                     N_TOK, DIM, HD);
    }
}